// round 7
// baseline (speedup 1.0000x reference)
#include <cuda_runtime.h>
#include <math.h>
#include <stdint.h>

#define T_STEPS 2048
#define BATCH   64
#define HID     256
#define GATE4   1024
#define NG      (BATCH*HID)          /* 16384 */
#define REC_THREADS 512
#define GST     5                    /* gates_sm row stride (floats) */

typedef unsigned long long u64;

/* Scratch (device globals: no allocation allowed in kernel_launch) */
__device__ float g_xg[134217728];    /* [T][B][4H] precomputed input gates */

/* ---- packed f32x2 helpers ---- */
__device__ __forceinline__ u64 ffma2(u64 a, u64 b, u64 c){
  u64 d; asm("fma.rn.f32x2 %0, %1, %2, %3;" : "=l"(d) : "l"(a), "l"(b), "l"(c));
  return d;
}
__device__ __forceinline__ u64 fmul2(u64 a, u64 b){
  u64 d; asm("mul.rn.f32x2 %0, %1, %2;" : "=l"(d) : "l"(a), "l"(b));
  return d;
}
__device__ __forceinline__ u64 fadd2(u64 a, u64 b){
  u64 d; asm("add.rn.f32x2 %0, %1, %2;" : "=l"(d) : "l"(a), "l"(b));
  return d;
}
__device__ __forceinline__ float hadd2(u64 a){
  unsigned lo, hi;
  asm("mov.b64 {%0, %1}, %2;" : "=r"(lo), "=r"(hi) : "l"(a));
  return __uint_as_float(lo) + __uint_as_float(hi);
}

__device__ __forceinline__ float fsigm(float x){
  return __fdividef(1.f, 1.f + __expf(-x));
}
__device__ __forceinline__ float ftanh(float x){
  return __fdividef(2.f, 1.f + __expf(-2.f*x)) - 1.f;
}

/* ---- cluster / DSMEM / mbarrier helpers ---- */
__device__ __forceinline__ uint32_t smem_u32(const void* p){
  uint32_t a;
  asm("{ .reg .u64 t; cvta.to.shared.u64 t, %1; cvt.u32.u64 %0, t; }"
      : "=r"(a) : "l"(p));
  return a;
}
__device__ __forceinline__ uint32_t mapa_rank(uint32_t addr, uint32_t rk){
  uint32_t r;
  asm("mapa.shared::cluster.u32 %0, %1, %2;" : "=r"(r) : "r"(addr), "r"(rk));
  return r;
}
__device__ __forceinline__ uint32_t ctarank(){
  uint32_t r; asm("mov.u32 %0, %%cluster_ctarank;" : "=r"(r)); return r;
}
__device__ __forceinline__ void st_cluster_v4(uint32_t addr, float4 v){
  asm volatile("st.shared::cluster.v4.f32 [%0], {%1,%2,%3,%4};"
               :: "r"(addr), "f"(v.x), "f"(v.y), "f"(v.z), "f"(v.w) : "memory");
}
__device__ __forceinline__ void mbar_init(uint32_t addr, unsigned cnt){
  asm volatile("mbarrier.init.shared.b64 [%0], %1;" :: "r"(addr), "r"(cnt) : "memory");
}
__device__ __forceinline__ void mbar_arrive_rel_cluster(uint32_t addr){
  asm volatile("mbarrier.arrive.release.cluster.shared::cluster.b64 _, [%0];"
               :: "r"(addr) : "memory");
}
__device__ __forceinline__ void mbar_wait(uint32_t addr, unsigned parity){
  unsigned done;
  asm volatile("{\n\t.reg .pred p;\n\t"
    "mbarrier.try_wait.parity.acquire.cluster.shared::cta.b64 p, [%1], %2;\n\t"
    "selp.b32 %0, 1, 0, p;\n\t}"
    : "=r"(done) : "r"(addr), "r"(parity) : "memory");
  if (!done){
    asm volatile("{\n\t.reg .pred P1;\n\t"
      "WL%=:\n\t"
      "mbarrier.try_wait.parity.acquire.cluster.shared::cta.b64 P1, [%0], %1;\n\t"
      "@P1 bra.uni WD%=;\n\t"
      "bra.uni WL%=;\n\t"
      "WD%=:\n\t}"
      :: "r"(addr), "r"(parity) : "memory");
  }
}

/* ---------------- Kernel A: x_gates = input @ W_ih^T + b_ih + b_hh ----------------
 * Round-3 plain-FFMA version (measured ~2.0ms, fp32 SIMT roofline). */
__global__ void __launch_bounds__(256, 2) xgates_gemm(
    const float* __restrict__ A, const float* __restrict__ W,
    const float* __restrict__ bih, const float* __restrict__ bhh)
{
  __shared__ float a_t[16][132];
  __shared__ float b_t[16][68];
  const int tid = threadIdx.x;
  const int bx = blockIdx.x, by = blockIdx.y;
  const int tx = tid & 15, ty = tid >> 4;

  float acc[8][4];
  #pragma unroll
  for (int m=0;m<8;m++)
    #pragma unroll
    for (int n=0;n<4;n++) acc[m][n]=0.f;

  const float* Ab = A + (size_t)by*128*256;
  const float* Wb = W + (size_t)bx*64*256;

  for (int kt=0; kt<16; ++kt){
    const int k0 = kt*16;
    #pragma unroll
    for (int r=0;r<2;r++){
      int idx = tid + r*256;
      int row = idx >> 2, kq = idx & 3;
      float4 v = *(const float4*)(Ab + (size_t)row*256 + k0 + kq*4);
      a_t[kq*4+0][row]=v.x; a_t[kq*4+1][row]=v.y;
      a_t[kq*4+2][row]=v.z; a_t[kq*4+3][row]=v.w;
    }
    {
      int n = tid >> 2, kq = tid & 3;
      float4 v = *(const float4*)(Wb + (size_t)n*256 + k0 + kq*4);
      b_t[kq*4+0][n]=v.x; b_t[kq*4+1][n]=v.y;
      b_t[kq*4+2][n]=v.z; b_t[kq*4+3][n]=v.w;
    }
    __syncthreads();
    #pragma unroll
    for (int k=0;k<16;k++){
      float af[8], bf[4];
      *(float4*)(af)   = *(const float4*)&a_t[k][ty*8];
      *(float4*)(af+4) = *(const float4*)&a_t[k][ty*8+4];
      *(float4*)(bf)   = *(const float4*)&b_t[k][tx*4];
      #pragma unroll
      for (int m=0;m<8;m++)
        #pragma unroll
        for (int n=0;n<4;n++)
          acc[m][n] += af[m]*bf[n];
    }
    __syncthreads();
  }

  const int gn = bx*64 + tx*4;
  const float bb0 = bih[gn+0]+bhh[gn+0];
  const float bb1 = bih[gn+1]+bhh[gn+1];
  const float bb2 = bih[gn+2]+bhh[gn+2];
  const float bb3 = bih[gn+3]+bhh[gn+3];
  #pragma unroll
  for (int m=0;m<8;m++){
    int gm = by*128 + ty*8 + m;
    float4 o = make_float4(acc[m][0]+bb0, acc[m][1]+bb1, acc[m][2]+bb2, acc[m][3]+bb3);
    *(float4*)(g_xg + (size_t)gm*GATE4 + gn) = o;
  }
}

/* ---------------- Kernel B: cluster recurrence, DSMEM push + mbarriers ----------
 * 16 chains = 16 clusters of 8 CTAs. CTA owns 4 batches x 32 j x 4 gates
 * (128 gate-rows; W slice in regs, 64 floats/lane). h lives only in SMEM,
 * double-buffered; handoff = 32 st.shared::cluster.v4 per peer + mbarrier.
 * full[i] (256 arrivals = 32/producer CTA, release.cluster) signals h ready;
 * empty[i] (8 arrivals) guards buffer reuse. Wait parity at step t for both
 * is ((t-1)>>1)&1. No global sync, no global h traffic.
 * Compute loop identical to R6: 4 passes x (4 LDS.128 + 32 FFMA2 + 8 SHFL). */
__global__ void __launch_bounds__(REC_THREADS, 1) __cluster_dims__(8, 1, 1)
lstm_rec(const float* __restrict__ h0, const float* __restrict__ c0,
         const float* __restrict__ W_hh, float* __restrict__ out)
{
  __shared__ __align__(16) float h_buf[2][4][256];   /* 8KB, [buf][b][j] */
  __shared__ __align__(16) float h_out[4][32];       /* this CTA's new h */
  __shared__ float gates_sm[128*GST];
  __shared__ __align__(8) u64 mbar[4];   /* full0, full1, empty0, empty1 */

  const int tid  = threadIdx.x;
  const uint32_t rank = ctarank();
  const int chain = blockIdx.x >> 3;
  const int b0   = chain*4;
  const int j0   = (int)rank*32;

  const int wid  = tid >> 5, lane = tid & 31;
  const int lg   = lane & 15, rh = lane >> 4;

  const uint32_t mbar_u = smem_u32(mbar);
  const uint32_t hbuf_u = smem_u32(h_buf);

  if (tid == 0){
    mbar_init(mbar_u,      256);  /* full0 */
    mbar_init(mbar_u + 8,  256);  /* full1 */
    mbar_init(mbar_u + 16,   8);  /* empty0 */
    mbar_init(mbar_u + 24,   8);  /* empty1 */
  }

  /* W_hh slice -> registers. rl in [0,128): gate = rl>>5, j = j0 + (rl&31). */
  ulonglong2 wr2[4][4];
  #pragma unroll
  for (int r=0;r<4;r++){
    const int rl = wid*8 + rh*4 + r;
    const int grow = (rl>>5)*HID + j0 + (rl&31);
    #pragma unroll
    for (int q=0;q<4;q++)
      wr2[r][q] = *(const ulonglong2*)(W_hh + (size_t)grow*HID + lg*4 + 64*q);
  }

  /* stage h0 (all 4 chain batches) into h_buf[0] */
  if (tid < 256){
    const int b = tid >> 6, k4 = tid & 63;
    *(float4*)&h_buf[0][b][k4*4] =
        *(const float4*)(h0 + (size_t)(b0+b)*HID + k4*4);
  }

  /* pusher setup: tid<256, peer = tid>>5, idx = tid&31 -> (b, jq) float4 */
  const int pr  = tid >> 5;           /* peer rank for pushes (warps 0-7) */
  const int pidx = tid & 31;
  const int pb  = pidx >> 3, pjq = pidx & 7;
  uint32_t peerH = 0, peerBarP = 0, peerBarE = 0;
  if (tid < 256){
    peerH    = mapa_rank(hbuf_u, (uint32_t)pr);
    peerBarP = mapa_rank(mbar_u, (uint32_t)pr);
  }
  if (tid < 8) peerBarE = mapa_rank(mbar_u, (uint32_t)tid);
  const uint32_t push_off0 = (uint32_t)((pb*256 + j0 + pjq*4) * 4);

  /* epilogue ownership: tid<128 owns (b = tid>>5, jl = tid&31) */
  const int jl = tid & 31, ebi = (tid >> 5) & 3;
  const int eb = b0 + ebi, ej = j0 + jl;
  float c_reg = 0.f, xg0=0.f, xg1=0.f, xg2=0.f, xg3=0.f;
  if (tid < 128){
    c_reg = c0[eb*HID + ej];
    const float* xp = g_xg + (size_t)eb*GATE4 + ej;   /* t = 0 */
    xg0 = xp[0]; xg1 = xp[HID]; xg2 = xp[2*HID]; xg3 = xp[3*HID];
  }

  __syncthreads();
  /* all mbarriers + h_buf[0] initialized cluster-wide before any remote op */
  asm volatile("barrier.cluster.arrive.aligned;" ::: "memory");
  asm volatile("barrier.cluster.wait.aligned;"   ::: "memory");

  for (int t=0; t<T_STEPS; ++t){
    const unsigned wp = (unsigned)(((t-1)>>1) & 1);

    /* ---- wait for this step's h (full[t&1]); acquire.cluster */
    if (t) mbar_wait(mbar_u + (unsigned)(t&1)*8, wp);

    /* ---- compute: 4 batch passes; 8 rows per warp (rh picks 4), FFMA2 */
    #pragma unroll
    for (int b=0;b<4;b++){
      const float* hb = h_buf[t&1][b] + lg*4;
      ulonglong2 hv0 = *(const ulonglong2*)(hb);
      ulonglong2 hv1 = *(const ulonglong2*)(hb+64);
      ulonglong2 hv2 = *(const ulonglong2*)(hb+128);
      ulonglong2 hv3 = *(const ulonglong2*)(hb+192);
      float v0, v1, v2, v3;
      #pragma unroll
      for (int r=0;r<4;r++){
        u64 s0 = fmul2(wr2[r][0].x, hv0.x);
        u64 s1 = fmul2(wr2[r][0].y, hv0.y);
        s0 = ffma2(wr2[r][1].x, hv1.x, s0);
        s1 = ffma2(wr2[r][1].y, hv1.y, s1);
        s0 = ffma2(wr2[r][2].x, hv2.x, s0);
        s1 = ffma2(wr2[r][2].y, hv2.y, s1);
        s0 = ffma2(wr2[r][3].x, hv3.x, s0);
        s1 = ffma2(wr2[r][3].y, hv3.y, s1);
        float v = hadd2(fadd2(s0, s1));
        if (r==0) v0=v; else if (r==1) v1=v; else if (r==2) v2=v; else v3=v;
      }
      v0 += __shfl_xor_sync(0xffffffffu, v0, 8);
      v1 += __shfl_xor_sync(0xffffffffu, v1, 8);
      v2 += __shfl_xor_sync(0xffffffffu, v2, 8);
      v3 += __shfl_xor_sync(0xffffffffu, v3, 8);
      float a  = (lg & 8) ? v1 : v0;
      float bb = (lg & 8) ? v3 : v2;
      a  += __shfl_xor_sync(0xffffffffu, a, 4);
      bb += __shfl_xor_sync(0xffffffffu, bb, 4);
      float x = (lg & 4) ? bb : a;
      x += __shfl_xor_sync(0xffffffffu, x, 2);
      x += __shfl_xor_sync(0xffffffffu, x, 1);
      if ((lg & 3) == 0){
        const int rsel = ((lg>>3)&1) | (((lg>>2)&1)<<1);   /* 0,8,4,12 -> 0..3 */
        gates_sm[(wid*8 + rh*4 + rsel)*GST + b] = x;
      }
    }
    __syncthreads();   /* A: all h_buf[t&1] reads done; gates_sm ready */

    /* ---- signal "done reading buf[t&1]" to every peer (empty[t&1]) */
    if (t < T_STEPS-1 && tid < 8)
      mbar_arrive_rel_cluster(peerBarE + 16u + (unsigned)(t&1)*8);

    /* ---- epilogue: activations + state update; h_out in local smem */
    float hn = 0.f;
    if (tid < 128){
      float pi = gates_sm[(0*32+jl)*GST + ebi] + xg0;
      float pf = gates_sm[(1*32+jl)*GST + ebi] + xg1;
      float pg = gates_sm[(2*32+jl)*GST + ebi] + xg2;
      float po = gates_sm[(3*32+jl)*GST + ebi] + xg3;
      float ii = fsigm(pi), ff = fsigm(pf), gg = ftanh(pg), oo = fsigm(po);
      c_reg = ff*c_reg + ii*gg;
      hn = oo * ftanh(c_reg);
      h_out[ebi][jl] = hn;
    }
    __syncthreads();   /* B: h_out complete */

    /* ---- push h to all 8 cluster CTAs (1 v4 store per pushing thread) */
    if (t < T_STEPS-1){
      if (t) mbar_wait(mbar_u + 16u + (unsigned)((t-1)&1)*8, wp);  /* empty */
      if (tid < 256){
        float4 v = *(const float4*)&h_out[pb][pjq*4];
        st_cluster_v4(peerH + (unsigned)((t+1)&1)*4096u + push_off0, v);
        mbar_arrive_rel_cluster(peerBarP + (unsigned)((t+1)&1)*8);
      }
    }

    /* ---- out-stores + next xg prefetch in the push shadow */
    if (tid < 128){
      out[(size_t)t*NG + eb*HID + ej] = hn;
      if (t == T_STEPS-1){
        out[(size_t)T_STEPS*NG + eb*HID + ej]      = hn;     /* h_T */
        out[(size_t)T_STEPS*NG + NG + eb*HID + ej] = c_reg;  /* c_T */
      } else {
        const float* xp = g_xg + ((size_t)(t+1)*BATCH + eb)*GATE4 + ej;
        xg0 = xp[0]; xg1 = xp[HID]; xg2 = xp[2*HID]; xg3 = xp[3*HID];
      }
    }
  }

  /* keep SMEM alive until all remote ops in the cluster have landed */
  asm volatile("barrier.cluster.arrive.aligned;" ::: "memory");
  asm volatile("barrier.cluster.wait.aligned;"   ::: "memory");
}

extern "C" void kernel_launch(void* const* d_in, const int* in_sizes, int n_in,
                              void* d_out, int out_size)
{
  (void)in_sizes; (void)n_in; (void)out_size;
  const float* input = (const float*)d_in[0];
  const float* h0    = (const float*)d_in[1];
  const float* c0    = (const float*)d_in[2];
  const float* W_ih  = (const float*)d_in[3];
  const float* W_hh  = (const float*)d_in[4];
  const float* b_ih  = (const float*)d_in[5];
  const float* b_hh  = (const float*)d_in[6];
  float* out = (float*)d_out;

  xgates_gemm<<<dim3(16,1024), 256>>>(input, W_ih, b_ih, b_hh);
  lstm_rec<<<128, REC_THREADS>>>(h0, c0, W_hh, out);
}

// round 11
// speedup vs baseline: 1.6361x; 1.6361x over previous
#include <cuda_runtime.h>
#include <math.h>
#include <stdint.h>

#define T_STEPS 2048
#define BATCH   64
#define HID     256
#define GATE4   1024
#define NG      (BATCH*HID)          /* 16384 */
#define REC_BLOCKS 128
#define REC_THREADS 512
#define CHAIN_BLOCKS 8               /* blocks per chain (one 4-batch group) */
#define GST     5                    /* gates_sm row stride (floats) */

typedef unsigned long long u64;

/* Scratch (device globals: no allocation allowed in kernel_launch) */
__device__ float g_xg[134217728];    /* [T][B][4H] precomputed input gates */
__device__ float g_h[2][NG];         /* double-buffered recurrent h */
__device__ unsigned g_bar16[512];    /* 16 chain barriers, 128B apart */
__device__ unsigned g_done;          /* end-of-kernel reset rendezvous */

/* ---- packed f32x2 helpers ---- */
__device__ __forceinline__ u64 ffma2(u64 a, u64 b, u64 c){
  u64 d; asm("fma.rn.f32x2 %0, %1, %2, %3;" : "=l"(d) : "l"(a), "l"(b), "l"(c));
  return d;
}
__device__ __forceinline__ u64 fmul2(u64 a, u64 b){
  u64 d; asm("mul.rn.f32x2 %0, %1, %2;" : "=l"(d) : "l"(a), "l"(b));
  return d;
}
__device__ __forceinline__ u64 fadd2(u64 a, u64 b){
  u64 d; asm("add.rn.f32x2 %0, %1, %2;" : "=l"(d) : "l"(a), "l"(b));
  return d;
}
__device__ __forceinline__ float hadd2(u64 a){
  unsigned lo, hi;
  asm("mov.b64 {%0, %1}, %2;" : "=r"(lo), "=r"(hi) : "l"(a));
  return __uint_as_float(lo) + __uint_as_float(hi);
}
__device__ __forceinline__ void unpack2(u64 a, float& x, float& y){
  unsigned lo, hi;
  asm("mov.b64 {%0, %1}, %2;" : "=r"(lo), "=r"(hi) : "l"(a));
  x = __uint_as_float(lo); y = __uint_as_float(hi);
}
__device__ __forceinline__ u64 dup2(float x){
  u64 d; unsigned u = __float_as_uint(x);
  asm("mov.b64 %0, {%1, %1};" : "=l"(d) : "r"(u));
  return d;
}

__device__ __forceinline__ float fsigm(float x){
  return __fdividef(1.f, 1.f + __expf(-x));
}
__device__ __forceinline__ float ftanh(float x){
  return __fdividef(2.f, 1.f + __expf(-2.f*x)) - 1.f;
}
__device__ __forceinline__ unsigned ld_acq(const unsigned* p){
  unsigned v;
  asm volatile("ld.global.acquire.gpu.u32 %0, [%1];" : "=r"(v) : "l"(p) : "memory");
  return v;
}
__device__ __forceinline__ void red_rel_add(unsigned* p, unsigned v){
  asm volatile("red.release.gpu.global.add.u32 [%0], %1;" :: "l"(p), "r"(v) : "memory");
}

/* ---------------- Kernel A: x_gates = input @ W_ih^T + b_ih + b_hh ----------------
 * R3 float smem tiles (proven layout) + FFMA2 inner loop with register-side
 * dup2 (R4 proved the packed-accumulator math; R4's regression was the u64
 * smem staging, removed here). Per k: 3 LDS.128 + 4 dup2 + 16 FFMA2. */
__global__ void __launch_bounds__(256, 2) xgates_gemm(
    const float* __restrict__ A, const float* __restrict__ W,
    const float* __restrict__ bih, const float* __restrict__ bhh)
{
  __shared__ float a_t[16][132];   /* [k][m], 528B rows (16B multiple) */
  __shared__ float b_t[16][68];    /* [k][n], 272B rows (16B multiple) */
  const int tid = threadIdx.x;
  const int bx = blockIdx.x, by = blockIdx.y;
  const int tx = tid & 15, ty = tid >> 4;

  u64 acc2[4][4];                  /* [m-pair][n] packed accumulators */
  #pragma unroll
  for (int mp=0;mp<4;mp++)
    #pragma unroll
    for (int n=0;n<4;n++) acc2[mp][n]=0ull;

  const float* Ab = A + (size_t)by*128*256;
  const float* Wb = W + (size_t)bx*64*256;

  for (int kt=0; kt<16; ++kt){
    const int k0 = kt*16;
    #pragma unroll
    for (int r=0;r<2;r++){
      int idx = tid + r*256;
      int row = idx >> 2, kq = idx & 3;
      float4 v = *(const float4*)(Ab + (size_t)row*256 + k0 + kq*4);
      a_t[kq*4+0][row]=v.x; a_t[kq*4+1][row]=v.y;
      a_t[kq*4+2][row]=v.z; a_t[kq*4+3][row]=v.w;
    }
    {
      int n = tid >> 2, kq = tid & 3;
      float4 v = *(const float4*)(Wb + (size_t)n*256 + k0 + kq*4);
      b_t[kq*4+0][n]=v.x; b_t[kq*4+1][n]=v.y;
      b_t[kq*4+2][n]=v.z; b_t[kq*4+3][n]=v.w;
    }
    __syncthreads();
    #pragma unroll
    for (int k=0;k<16;k++){
      ulonglong2 a01 = *(const ulonglong2*)&a_t[k][ty*8];    /* (m0m1)(m2m3) */
      ulonglong2 a23 = *(const ulonglong2*)&a_t[k][ty*8+4];  /* (m4m5)(m6m7) */
      float4 bf = *(const float4*)&b_t[k][tx*4];
      u64 bd0 = dup2(bf.x), bd1 = dup2(bf.y), bd2 = dup2(bf.z), bd3 = dup2(bf.w);
      acc2[0][0]=ffma2(a01.x,bd0,acc2[0][0]); acc2[0][1]=ffma2(a01.x,bd1,acc2[0][1]);
      acc2[0][2]=ffma2(a01.x,bd2,acc2[0][2]); acc2[0][3]=ffma2(a01.x,bd3,acc2[0][3]);
      acc2[1][0]=ffma2(a01.y,bd0,acc2[1][0]); acc2[1][1]=ffma2(a01.y,bd1,acc2[1][1]);
      acc2[1][2]=ffma2(a01.y,bd2,acc2[1][2]); acc2[1][3]=ffma2(a01.y,bd3,acc2[1][3]);
      acc2[2][0]=ffma2(a23.x,bd0,acc2[2][0]); acc2[2][1]=ffma2(a23.x,bd1,acc2[2][1]);
      acc2[2][2]=ffma2(a23.x,bd2,acc2[2][2]); acc2[2][3]=ffma2(a23.x,bd3,acc2[2][3]);
      acc2[3][0]=ffma2(a23.y,bd0,acc2[3][0]); acc2[3][1]=ffma2(a23.y,bd1,acc2[3][1]);
      acc2[3][2]=ffma2(a23.y,bd2,acc2[3][2]); acc2[3][3]=ffma2(a23.y,bd3,acc2[3][3]);
    }
    __syncthreads();
  }

  const int gn = bx*64 + tx*4;
  const float bb0 = bih[gn+0]+bhh[gn+0];
  const float bb1 = bih[gn+1]+bhh[gn+1];
  const float bb2 = bih[gn+2]+bhh[gn+2];
  const float bb3 = bih[gn+3]+bhh[gn+3];
  #pragma unroll
  for (int mp=0;mp<4;mp++){
    float e0,o0,e1,o1,e2,o2,e3,o3;
    unpack2(acc2[mp][0], e0, o0);
    unpack2(acc2[mp][1], e1, o1);
    unpack2(acc2[mp][2], e2, o2);
    unpack2(acc2[mp][3], e3, o3);
    int gm = by*128 + ty*8 + 2*mp;
    float4 lo = make_float4(e0+bb0, e1+bb1, e2+bb2, e3+bb3);
    float4 hi = make_float4(o0+bb0, o1+bb1, o2+bb2, o3+bb3);
    *(float4*)(g_xg + (size_t)gm*GATE4 + gn)     = lo;
    *(float4*)(g_xg + (size_t)(gm+1)*GATE4 + gn) = hi;
  }
}

/* ---------------- Kernel B: persistent recurrence (R6, proven) ----------------
 * 16 independent chains x 8 blocks. Chain = one 4-batch group; block owns
 * 32 j x 4 gates = 128 gate-rows (W slice in regs, 64 floats/lane).
 * Handoff via L2: producers STG.cg h + release-red on the chain counter
 * (8 arrivals/step); consumers acquire-poll then stage 4KB of h. */
__global__ void __launch_bounds__(REC_THREADS, 1) lstm_rec(
    const float* __restrict__ h0, const float* __restrict__ c0,
    const float* __restrict__ W_hh, float* __restrict__ out)
{
  __shared__ float h_sm[4][256];         /* [local batch][k] : 4KB */
  __shared__ float gates_sm[128*GST];    /* [gate-row rl][b], rl = g*32+jl */

  const int tid  = threadIdx.x;
  const int blk  = blockIdx.x;
  const int bgid = blk & 15;             /* chain id (batch group) */
  const int jgid = blk >> 4;             /* j-group within chain   */
  const int b0   = bgid*4;
  const int j0   = jgid*32;
  unsigned* barp = &g_bar16[bgid*32];

  const int wid  = tid >> 5, lane = tid & 31;
  const int lg   = lane & 15, rh = lane >> 4;

  /* W_hh slice -> registers. rl in [0,128): gate = rl>>5, j = j0 + (rl&31). */
  ulonglong2 wr2[4][4];
  #pragma unroll
  for (int r=0;r<4;r++){
    const int rl = wid*8 + rh*4 + r;
    const int grow = (rl>>5)*HID + j0 + (rl&31);
    #pragma unroll
    for (int q=0;q<4;q++)
      wr2[r][q] = *(const ulonglong2*)(W_hh + (size_t)grow*HID + lg*4 + 64*q);
  }

  /* epilogue ownership: tid<128 owns (b = tid>>5, jl = tid&31) */
  const int jl = tid & 31, ebi = (tid >> 5) & 3;
  const int eb = b0 + ebi, ej = j0 + jl;
  float c_reg = 0.f, xg0=0.f, xg1=0.f, xg2=0.f, xg3=0.f;
  if (tid < 128){
    c_reg = c0[eb*HID + ej];
    const float* xp = g_xg + (size_t)eb*GATE4 + ej;   /* t = 0 */
    xg0 = xp[0]; xg1 = xp[HID]; xg2 = xp[2*HID]; xg3 = xp[3*HID];
  }

  for (int t=0; t<T_STEPS; ++t){
    /* ---- wait for previous step's h from this chain (acquire) */
    if (t){
      const unsigned target = (unsigned)t * CHAIN_BLOCKS;
      while (ld_acq(barp) < target) { }
    }

    /* ---- stage h: 4 batches x 256 = 4KB, tid<256 one float4 each (.cg) */
    if (tid < 256){
      const float4* hsrc = (const float4*)(((t==0) ? h0 : g_h[t & 1]) + b0*HID);
      const int b = tid >> 6, k4 = tid & 63;
      float4 v = __ldcg(hsrc + b*64 + k4);
      *(float4*)&h_sm[b][k4*4] = v;
    }
    __syncthreads();

    /* ---- compute: 4 batch passes; 8 rows per warp (rh picks 4), FFMA2 */
    #pragma unroll
    for (int b=0;b<4;b++){
      const float* hb = h_sm[b] + lg*4;
      ulonglong2 hv0 = *(const ulonglong2*)(hb);
      ulonglong2 hv1 = *(const ulonglong2*)(hb+64);
      ulonglong2 hv2 = *(const ulonglong2*)(hb+128);
      ulonglong2 hv3 = *(const ulonglong2*)(hb+192);
      float v0, v1, v2, v3;
      #pragma unroll
      for (int r=0;r<4;r++){
        u64 s0 = fmul2(wr2[r][0].x, hv0.x);
        u64 s1 = fmul2(wr2[r][0].y, hv0.y);
        s0 = ffma2(wr2[r][1].x, hv1.x, s0);
        s1 = ffma2(wr2[r][1].y, hv1.y, s1);
        s0 = ffma2(wr2[r][2].x, hv2.x, s0);
        s1 = ffma2(wr2[r][2].y, hv2.y, s1);
        s0 = ffma2(wr2[r][3].x, hv3.x, s0);
        s1 = ffma2(wr2[r][3].y, hv3.y, s1);
        float v = hadd2(fadd2(s0, s1));
        if (r==0) v0=v; else if (r==1) v1=v; else if (r==2) v2=v; else v3=v;
      }
      /* reduce 4 rows over the 16 k-lanes: 8 SHFL (rh bit untouched) */
      v0 += __shfl_xor_sync(0xffffffffu, v0, 8);
      v1 += __shfl_xor_sync(0xffffffffu, v1, 8);
      v2 += __shfl_xor_sync(0xffffffffu, v2, 8);
      v3 += __shfl_xor_sync(0xffffffffu, v3, 8);
      float a  = (lg & 8) ? v1 : v0;
      float bb = (lg & 8) ? v3 : v2;
      a  += __shfl_xor_sync(0xffffffffu, a, 4);
      bb += __shfl_xor_sync(0xffffffffu, bb, 4);
      float x = (lg & 4) ? bb : a;
      x += __shfl_xor_sync(0xffffffffu, x, 2);
      x += __shfl_xor_sync(0xffffffffu, x, 1);
      if ((lg & 3) == 0){
        const int rsel = ((lg>>3)&1) | (((lg>>2)&1)<<1);   /* 0,8,4,12 -> 0..3 */
        gates_sm[(wid*8 + rh*4 + rsel)*GST + b] = x;
      }
    }
    __syncthreads();

    /* ---- epilogue: activations + state update (c stays in a register) */
    float hn = 0.f;
    if (tid < 128){
      float pi = gates_sm[(0*32+jl)*GST + ebi] + xg0;
      float pf = gates_sm[(1*32+jl)*GST + ebi] + xg1;
      float pg = gates_sm[(2*32+jl)*GST + ebi] + xg2;
      float po = gates_sm[(3*32+jl)*GST + ebi] + xg3;
      float ii = fsigm(pi), ff = fsigm(pf), gg = ftanh(pg), oo = fsigm(po);
      c_reg = ff*c_reg + ii*gg;
      hn = oo * ftanh(c_reg);
      __stcg(&g_h[(t+1)&1][eb*HID + ej], hn);
    }
    __syncthreads();   /* h stores observed CTA-wide before tid0's release */

    /* ---- arrival (release), then out-stores + prefetch in its shadow */
    if (tid == 0) red_rel_add(barp, 1u);
    if (tid < 128){
      out[(size_t)t*NG + eb*HID + ej] = hn;
      if (t == T_STEPS-1){
        out[(size_t)T_STEPS*NG + eb*HID + ej]      = hn;     /* h_T */
        out[(size_t)T_STEPS*NG + NG + eb*HID + ej] = c_reg;  /* c_T */
      } else {
        const float* xp = g_xg + ((size_t)(t+1)*BATCH + eb)*GATE4 + ej;
        xg0 = xp[0]; xg1 = xp[HID]; xg2 = xp[2*HID]; xg3 = xp[3*HID];
      }
    }
  }

  /* reset counters for the next graph replay: last block to arrive does it */
  if (tid == 0){
    __threadfence();
    unsigned prev = atomicAdd(&g_done, 1u);
    if (prev == REC_BLOCKS-1){
      #pragma unroll
      for (int ch=0; ch<16; ch++) g_bar16[ch*32] = 0u;
      g_done = 0u;
      __threadfence();
    }
  }
}

extern "C" void kernel_launch(void* const* d_in, const int* in_sizes, int n_in,
                              void* d_out, int out_size)
{
  (void)in_sizes; (void)n_in; (void)out_size;
  const float* input = (const float*)d_in[0];
  const float* h0    = (const float*)d_in[1];
  const float* c0    = (const float*)d_in[2];
  const float* W_ih  = (const float*)d_in[3];
  const float* W_hh  = (const float*)d_in[4];
  const float* b_ih  = (const float*)d_in[5];
  const float* b_hh  = (const float*)d_in[6];
  float* out = (float*)d_out;

  xgates_gemm<<<dim3(16,1024), 256>>>(input, W_ih, b_ih, b_hh);
  lstm_rec<<<REC_BLOCKS, REC_THREADS>>>(h0, c0, W_hh, out);
}

// round 13
// speedup vs baseline: 1.8071x; 1.1045x over previous
#include <cuda_runtime.h>
#include <cuda_bf16.h>
#include <math.h>
#include <stdint.h>

#define T_STEPS 2048
#define BATCH   64
#define HID     256
#define GATE4   1024
#define NG      (BATCH*HID)          /* 16384 */
#define REC_BLOCKS 128
#define REC_THREADS 512
#define CHAIN_BLOCKS 8
#define GST     5
#define APAD    40                   /* bf16 row stride: 80B, conflict-free */

typedef unsigned long long u64;

/* Scratch (device globals: no allocation allowed in kernel_launch) */
__device__ float g_xg[134217728];    /* [T][B][4H] precomputed input gates */
__device__ float g_h[2][NG];         /* double-buffered recurrent h */
__device__ unsigned g_bar16[512];    /* 16 chain barriers, 128B apart */
__device__ unsigned g_done;          /* end-of-kernel reset rendezvous */

/* ---- packed f32x2 helpers (recurrence) ---- */
__device__ __forceinline__ u64 ffma2(u64 a, u64 b, u64 c){
  u64 d; asm("fma.rn.f32x2 %0, %1, %2, %3;" : "=l"(d) : "l"(a), "l"(b), "l"(c));
  return d;
}
__device__ __forceinline__ u64 fmul2(u64 a, u64 b){
  u64 d; asm("mul.rn.f32x2 %0, %1, %2;" : "=l"(d) : "l"(a), "l"(b));
  return d;
}
__device__ __forceinline__ u64 fadd2(u64 a, u64 b){
  u64 d; asm("add.rn.f32x2 %0, %1, %2;" : "=l"(d) : "l"(a), "l"(b));
  return d;
}
__device__ __forceinline__ float hadd2(u64 a){
  unsigned lo, hi;
  asm("mov.b64 {%0, %1}, %2;" : "=r"(lo), "=r"(hi) : "l"(a));
  return __uint_as_float(lo) + __uint_as_float(hi);
}
__device__ __forceinline__ float fsigm(float x){
  return __fdividef(1.f, 1.f + __expf(-x));
}
__device__ __forceinline__ float ftanh(float x){
  return __fdividef(2.f, 1.f + __expf(-2.f*x)) - 1.f;
}
__device__ __forceinline__ unsigned ld_acq(const unsigned* p){
  unsigned v;
  asm volatile("ld.global.acquire.gpu.u32 %0, [%1];" : "=r"(v) : "l"(p) : "memory");
  return v;
}
__device__ __forceinline__ void red_rel_add(unsigned* p, unsigned v){
  asm volatile("red.release.gpu.global.add.u32 [%0], %1;" :: "l"(p), "r"(v) : "memory");
}

/* ---- HMMA / ldmatrix helpers (baseline PTX, valid on compute_103) ---- */
__device__ __forceinline__ uint32_t smem_u32(const void* p){
  uint32_t a;
  asm("{ .reg .u64 t; cvta.to.shared.u64 t, %1; cvt.u32.u64 %0, t; }"
      : "=r"(a) : "l"(p));
  return a;
}
__device__ __forceinline__ void ldsm_x4(uint32_t* r, uint32_t addr){
  asm volatile("ldmatrix.sync.aligned.m8n8.x4.shared.b16 {%0,%1,%2,%3}, [%4];"
    : "=r"(r[0]), "=r"(r[1]), "=r"(r[2]), "=r"(r[3]) : "r"(addr));
}
__device__ __forceinline__ void ldsm_x2(uint32_t* r, uint32_t addr){
  asm volatile("ldmatrix.sync.aligned.m8n8.x2.shared.b16 {%0,%1}, [%2];"
    : "=r"(r[0]), "=r"(r[1]) : "r"(addr));
}
__device__ __forceinline__ void mma16816(float* d, const uint32_t* a, const uint32_t* b){
  asm volatile(
    "mma.sync.aligned.m16n8k16.row.col.f32.bf16.bf16.f32 "
    "{%0,%1,%2,%3}, {%4,%5,%6,%7}, {%8,%9}, {%0,%1,%2,%3};"
    : "+f"(d[0]), "+f"(d[1]), "+f"(d[2]), "+f"(d[3])
    : "r"(a[0]), "r"(a[1]), "r"(a[2]), "r"(a[3]), "r"(b[0]), "r"(b[1]));
}
/* split 4 consecutive fp32 k-values into bf16 hi/lo and store as u64 pairs */
__device__ __forceinline__ void split40(__nv_bfloat16* hi, __nv_bfloat16* lo,
                                        int row, int col, float4 v){
  __nv_bfloat16 h0=__float2bfloat16(v.x), h1=__float2bfloat16(v.y),
                h2=__float2bfloat16(v.z), h3=__float2bfloat16(v.w);
  float r0=v.x-__bfloat162float(h0), r1=v.y-__bfloat162float(h1),
        r2=v.z-__bfloat162float(h2), r3=v.w-__bfloat162float(h3);
  __nv_bfloat16 l0=__float2bfloat16(r0), l1=__float2bfloat16(r1),
                l2=__float2bfloat16(r2), l3=__float2bfloat16(r3);
  u64 hw = (u64)__bfloat16_as_ushort(h0)       | ((u64)__bfloat16_as_ushort(h1)<<16)
         | ((u64)__bfloat16_as_ushort(h2)<<32) | ((u64)__bfloat16_as_ushort(h3)<<48);
  u64 lw = (u64)__bfloat16_as_ushort(l0)       | ((u64)__bfloat16_as_ushort(l1)<<16)
         | ((u64)__bfloat16_as_ushort(l2)<<32) | ((u64)__bfloat16_as_ushort(l3)<<48);
  *(u64*)(hi + row*APAD + col) = hw;
  *(u64*)(lo + row*APAD + col) = lw;
}

/* ---------------- Kernel A: x_gates via mma.sync bf16 3-term split ----------
 * D = A_hi.B_hi + A_hi.B_lo + A_lo.B_hi  (fp32-accurate, err ~2^-17).
 * CTA tile 128(M) x 64(N); 8 warps = 4m x 2n, warp tile 32x32 = 2x4 mma
 * m16n8k16 tiles. K = 8 chunks x 32 fp32; per chunk staged to bf16 hi/lo
 * padded smem (stride 40), then 2 k16-steps x 24 mma per warp.
 * A frags: ldmatrix.x4 row-major; B frags: ldmatrix.x2 on [n][k] (= col-
 * major operand). TN fragment layouts per PTX ISA. */
__global__ void __launch_bounds__(256) xgates_mma(
    const float* __restrict__ A, const float* __restrict__ W,
    const float* __restrict__ bih, const float* __restrict__ bhh)
{
  __shared__ __align__(16) __nv_bfloat16 sA[2][128][APAD];  /* [hi/lo][m][k] */
  __shared__ __align__(16) __nv_bfloat16 sB[2][64][APAD];   /* [hi/lo][n][k] */
  __shared__ float bias_sm[64];

  const int tid = threadIdx.x;
  const int wid = tid >> 5, lane = tid & 31;
  const int bx = blockIdx.x, by = blockIdx.y;
  const int wm = wid >> 1, wn = wid & 1;

  if (tid < 64) bias_sm[tid] = bih[(bx<<6) + tid] + bhh[(bx<<6) + tid];

  float acc[2][4][4];
  #pragma unroll
  for (int mi=0;mi<2;mi++)
    #pragma unroll
    for (int ni=0;ni<4;ni++)
      #pragma unroll
      for (int e=0;e<4;e++) acc[mi][ni][e] = 0.f;

  const uint32_t aHi = smem_u32(&sA[0][0][0]);
  const uint32_t aLo = smem_u32(&sA[1][0][0]);
  const uint32_t bHi = smem_u32(&sB[0][0][0]);
  const uint32_t bLo = smem_u32(&sB[1][0][0]);

  /* per-thread ldmatrix address bases (byte offsets; APAD*2 = 80 B rows) */
  const int arow = wm*32 + (lane&7) + ((lane>>3)&1)*8;
  const uint32_t aoff = (uint32_t)(arow*80 + ((lane>>4)*8)*2);
  const int brow = wn*32 + (lane&7);
  const uint32_t boff = (uint32_t)(brow*80 + (((lane>>3)&1)*8)*2);

  const float* Ab = A + (size_t)(by<<7)*256;
  const float* Wb = W + (size_t)(bx<<6)*256;

  for (int kc = 0; kc < 8; ++kc){
    /* stage A chunk 128x32: thread -> row tid>>1, cols (tid&1)*16 + q*4 */
    {
      const int row = tid >> 1, ch = (tid & 1) << 4;
      const float* src = Ab + (size_t)row*256 + (kc<<5) + ch;
      #pragma unroll
      for (int q=0;q<4;q++)
        split40(&sA[0][0][0], &sA[1][0][0], row, ch + (q<<2),
                *(const float4*)(src + (q<<2)));
    }
    /* stage B chunk 64x32: thread -> row tid>>2, cols (tid&3)*8 + q*4 */
    {
      const int row = tid >> 2, ch = (tid & 3) << 3;
      const float* src = Wb + (size_t)row*256 + (kc<<5) + ch;
      #pragma unroll
      for (int q=0;q<2;q++)
        split40(&sB[0][0][0], &sB[1][0][0], row, ch + (q<<2),
                *(const float4*)(src + (q<<2)));
    }
    __syncthreads();

    #pragma unroll
    for (int kh=0; kh<2; ++kh){
      const uint32_t k2 = (uint32_t)(kh<<5);    /* 16 bf16 = 32 bytes */
      uint32_t ah[2][4], al[2][4], bh[4][2], bl[4][2];
      #pragma unroll
      for (int mi=0;mi<2;mi++){
        ldsm_x4(ah[mi], aHi + aoff + (uint32_t)(mi*16*80) + k2);
        ldsm_x4(al[mi], aLo + aoff + (uint32_t)(mi*16*80) + k2);
      }
      #pragma unroll
      for (int ni=0;ni<4;ni++){
        ldsm_x2(bh[ni], bHi + boff + (uint32_t)(ni*8*80) + k2);
        ldsm_x2(bl[ni], bLo + boff + (uint32_t)(ni*8*80) + k2);
      }
      #pragma unroll
      for (int mi=0;mi<2;mi++)
        #pragma unroll
        for (int ni=0;ni<4;ni++){
          mma16816(acc[mi][ni], ah[mi], bh[ni]);
          mma16816(acc[mi][ni], ah[mi], bl[ni]);
          mma16816(acc[mi][ni], al[mi], bh[ni]);
        }
    }
    __syncthreads();
  }

  /* epilogue: D fragment rows = t/4 (+8), cols = 2*(t%4) (+1) */
  const int r0 = lane >> 2, c0 = (lane & 3) << 1;
  #pragma unroll
  for (int mi=0;mi<2;mi++){
    const int grow = (by<<7) + wm*32 + mi*16 + r0;
    #pragma unroll
    for (int ni=0;ni<4;ni++){
      const int lc = wn*32 + ni*8 + c0;
      const int gcol = (bx<<6) + lc;
      float2 o0, o1;
      o0.x = acc[mi][ni][0] + bias_sm[lc];
      o0.y = acc[mi][ni][1] + bias_sm[lc+1];
      o1.x = acc[mi][ni][2] + bias_sm[lc];
      o1.y = acc[mi][ni][3] + bias_sm[lc+1];
      *(float2*)(g_xg + (size_t)grow*GATE4 + gcol)     = o0;
      *(float2*)(g_xg + (size_t)(grow+8)*GATE4 + gcol) = o1;
    }
  }
}

/* ---------------- Kernel B: persistent recurrence (R6/R11, proven 3x) ------- */
__global__ void __launch_bounds__(REC_THREADS, 1) lstm_rec(
    const float* __restrict__ h0, const float* __restrict__ c0,
    const float* __restrict__ W_hh, float* __restrict__ out)
{
  __shared__ float h_sm[4][256];
  __shared__ float gates_sm[128*GST];

  const int tid  = threadIdx.x;
  const int blk  = blockIdx.x;
  const int bgid = blk & 15;
  const int jgid = blk >> 4;
  const int b0   = bgid*4;
  const int j0   = jgid*32;
  unsigned* barp = &g_bar16[bgid*32];

  const int wid  = tid >> 5, lane = tid & 31;
  const int lg   = lane & 15, rh = lane >> 4;

  ulonglong2 wr2[4][4];
  #pragma unroll
  for (int r=0;r<4;r++){
    const int rl = wid*8 + rh*4 + r;
    const int grow = (rl>>5)*HID + j0 + (rl&31);
    #pragma unroll
    for (int q=0;q<4;q++)
      wr2[r][q] = *(const ulonglong2*)(W_hh + (size_t)grow*HID + lg*4 + 64*q);
  }

  const int jl = tid & 31, ebi = (tid >> 5) & 3;
  const int eb = b0 + ebi, ej = j0 + jl;
  float c_reg = 0.f, xg0=0.f, xg1=0.f, xg2=0.f, xg3=0.f;
  if (tid < 128){
    c_reg = c0[eb*HID + ej];
    const float* xp = g_xg + (size_t)eb*GATE4 + ej;
    xg0 = xp[0]; xg1 = xp[HID]; xg2 = xp[2*HID]; xg3 = xp[3*HID];
  }

  for (int t=0; t<T_STEPS; ++t){
    if (t){
      const unsigned target = (unsigned)t * CHAIN_BLOCKS;
      while (ld_acq(barp) < target) { }
    }

    if (tid < 256){
      const float4* hsrc = (const float4*)(((t==0) ? h0 : g_h[t & 1]) + b0*HID);
      const int b = tid >> 6, k4 = tid & 63;
      float4 v = __ldcg(hsrc + b*64 + k4);
      *(float4*)&h_sm[b][k4*4] = v;
    }
    __syncthreads();

    #pragma unroll
    for (int b=0;b<4;b++){
      const float* hb = h_sm[b] + lg*4;
      ulonglong2 hv0 = *(const ulonglong2*)(hb);
      ulonglong2 hv1 = *(const ulonglong2*)(hb+64);
      ulonglong2 hv2 = *(const ulonglong2*)(hb+128);
      ulonglong2 hv3 = *(const ulonglong2*)(hb+192);
      float v0, v1, v2, v3;
      #pragma unroll
      for (int r=0;r<4;r++){
        u64 s0 = fmul2(wr2[r][0].x, hv0.x);
        u64 s1 = fmul2(wr2[r][0].y, hv0.y);
        s0 = ffma2(wr2[r][1].x, hv1.x, s0);
        s1 = ffma2(wr2[r][1].y, hv1.y, s1);
        s0 = ffma2(wr2[r][2].x, hv2.x, s0);
        s1 = ffma2(wr2[r][2].y, hv2.y, s1);
        s0 = ffma2(wr2[r][3].x, hv3.x, s0);
        s1 = ffma2(wr2[r][3].y, hv3.y, s1);
        float v = hadd2(fadd2(s0, s1));
        if (r==0) v0=v; else if (r==1) v1=v; else if (r==2) v2=v; else v3=v;
      }
      v0 += __shfl_xor_sync(0xffffffffu, v0, 8);
      v1 += __shfl_xor_sync(0xffffffffu, v1, 8);
      v2 += __shfl_xor_sync(0xffffffffu, v2, 8);
      v3 += __shfl_xor_sync(0xffffffffu, v3, 8);
      float a  = (lg & 8) ? v1 : v0;
      float bb = (lg & 8) ? v3 : v2;
      a  += __shfl_xor_sync(0xffffffffu, a, 4);
      bb += __shfl_xor_sync(0xffffffffu, bb, 4);
      float x = (lg & 4) ? bb : a;
      x += __shfl_xor_sync(0xffffffffu, x, 2);
      x += __shfl_xor_sync(0xffffffffu, x, 1);
      if ((lg & 3) == 0){
        const int rsel = ((lg>>3)&1) | (((lg>>2)&1)<<1);
        gates_sm[(wid*8 + rh*4 + rsel)*GST + b] = x;
      }
    }
    __syncthreads();

    float hn = 0.f;
    if (tid < 128){
      float pi = gates_sm[(0*32+jl)*GST + ebi] + xg0;
      float pf = gates_sm[(1*32+jl)*GST + ebi] + xg1;
      float pg = gates_sm[(2*32+jl)*GST + ebi] + xg2;
      float po = gates_sm[(3*32+jl)*GST + ebi] + xg3;
      float ii = fsigm(pi), ff = fsigm(pf), gg = ftanh(pg), oo = fsigm(po);
      c_reg = ff*c_reg + ii*gg;
      hn = oo * ftanh(c_reg);
      __stcg(&g_h[(t+1)&1][eb*HID + ej], hn);
    }
    __syncthreads();

    if (tid == 0) red_rel_add(barp, 1u);
    if (tid < 128){
      out[(size_t)t*NG + eb*HID + ej] = hn;
      if (t == T_STEPS-1){
        out[(size_t)T_STEPS*NG + eb*HID + ej]      = hn;
        out[(size_t)T_STEPS*NG + NG + eb*HID + ej] = c_reg;
      } else {
        const float* xp = g_xg + ((size_t)(t+1)*BATCH + eb)*GATE4 + ej;
        xg0 = xp[0]; xg1 = xp[HID]; xg2 = xp[2*HID]; xg3 = xp[3*HID];
      }
    }
  }

  if (tid == 0){
    __threadfence();
    unsigned prev = atomicAdd(&g_done, 1u);
    if (prev == REC_BLOCKS-1){
      #pragma unroll
      for (int ch=0; ch<16; ch++) g_bar16[ch*32] = 0u;
      g_done = 0u;
      __threadfence();
    }
  }
}

extern "C" void kernel_launch(void* const* d_in, const int* in_sizes, int n_in,
                              void* d_out, int out_size)
{
  (void)in_sizes; (void)n_in; (void)out_size;
  const float* input = (const float*)d_in[0];
  const float* h0    = (const float*)d_in[1];
  const float* c0    = (const float*)d_in[2];
  const float* W_ih  = (const float*)d_in[3];
  const float* W_hh  = (const float*)d_in[4];
  const float* b_ih  = (const float*)d_in[5];
  const float* b_hh  = (const float*)d_in[6];
  float* out = (float*)d_out;

  xgates_mma<<<dim3(16,1024), 256>>>(input, W_ih, b_ih, b_hh);
  lstm_rec<<<REC_BLOCKS, REC_THREADS>>>(h0, c0, W_hh, out);
}